// round 13
// baseline (speedup 1.0000x reference)
#include <cuda_runtime.h>

#define BB 2
#define QQ 8192
#define MM 65536

__device__ float g_feat[BB * 64 * 64 * 64];     // channel-last [b][y][x][c]
__device__ float g_X[MM * 4];
__device__ int   g_gidx[MM];
__device__ float g_score[MM];
__device__ float g_H1[(size_t)MM * 256];
__device__ float g_H2[(size_t)MM * 256];
__device__ int   g_lut[1728];

__device__ __forceinline__ float fast_gelu(float x) {
    float u = 1.5957691216057308f * fmaf(0.044715f * x * x, x, x);
    return x * __fdividef(1.0f, 1.0f + __expf(-u));
}

__device__ __forceinline__ float f2tf32(float x) {
    unsigned u;
    asm("cvt.rna.tf32.f32 %0, %1;" : "=r"(u) : "f"(x));
    return __uint_as_float(u);
}

__device__ __forceinline__ void mma8(float* dd, unsigned a0, unsigned a1, unsigned a2,
                                     unsigned a3, unsigned b0, unsigned b1) {
    asm volatile(
        "mma.sync.aligned.m16n8k8.row.col.f32.tf32.tf32.f32 "
        "{%0,%1,%2,%3}, {%4,%5,%6,%7}, {%8,%9}, {%0,%1,%2,%3};\n"
        : "+f"(dd[0]), "+f"(dd[1]), "+f"(dd[2]), "+f"(dd[3])
        : "r"(a0), "r"(a1), "r"(a2), "r"(a3), "r"(b0), "r"(b1));
}

__device__ __forceinline__ unsigned fcomp(const float4& v, int j) {
    return __float_as_uint(((const float*)&v)[j]);
}

// K1: conv3x3 SAME + bias, channel-last feat
__global__ void conv_kernel(const float* __restrict__ inp,
                            const float* __restrict__ w,
                            const float* __restrict__ bias) {
    __shared__ float s_in[27];
    int pix = blockIdx.x;
    int b = pix >> 12, y = (pix >> 6) & 63, x = pix & 63;
    int c = threadIdx.x;
    if (c < 27) {
        int i = c / 9, kk = c - i * 9;
        int yy = y + kk / 3 - 1, xx = x + (kk % 3) - 1;
        float v = 0.f;
        if (yy >= 0 && yy < 64 && xx >= 0 && xx < 64)
            v = inp[((b * 3 + i) * 64 + yy) * 64 + xx];
        s_in[c] = v;
    }
    __syncthreads();
    float acc = bias[c];
#pragma unroll
    for (int t = 0; t < 27; t++) acc = fmaf(s_in[t], w[c * 27 + t], acc);
    g_feat[(pix << 6) + c] = acc;
}

// K2: prep + score MLP
__global__ void prep_kernel(const float* __restrict__ coord,
                            const float* __restrict__ scale,
                            const float* __restrict__ sw0,
                            const float* __restrict__ sb0,
                            const float* __restrict__ sw1,
                            const float* __restrict__ sb1) {
    int m = blockIdx.x * blockDim.x + threadIdx.x;
    if (m >= MM) return;
    int b = m >> 15, q = (m >> 2) & (QQ - 1), s = m & 3;
    float vx = (s < 2) ? -1.f : 1.f;
    float vy = (s & 1) ? 1.f : -1.f;

    float c0 = coord[(b * QQ + q) * 2 + 0];
    float c1 = coord[(b * QQ + q) * 2 + 1];
    float tx = 63.0f / (1.0f - scale[(size_t)b * QQ * 2 + 0]);
    float ty = 63.0f / (1.0f - scale[(size_t)b * QQ * 2 + 1]);
    float sh0 = vx * (1.0f / tx) + 1e-6f;
    float sh1 = vy * (1.0f / ty) + 1e-6f;

    float cc0 = fminf(fmaxf(c0 + sh0, -1.0f + 1e-6f), 1.0f - 1e-6f);
    float cc1 = fminf(fmaxf(c1 + sh1, -1.0f + 1e-6f), 1.0f - 1e-6f);
    int iy = (int)fminf(fmaxf(rintf((cc0 + 1.0f) * 32.0f - 0.5f), 0.f), 63.f);
    int ix = (int)fminf(fmaxf(rintf((cc1 + 1.0f) * 32.0f - 0.5f), 0.f), 63.f);

    float ck0 = -1.0f + (float)(2 * iy + 1) * 0.015625f;
    float ck1 = -1.0f + (float)(2 * ix + 1) * 0.015625f;
    float relx = (c0 - ck0) * 64.0f;
    float rely = (c1 - ck1) * 64.0f;
    float st0 = scale[(size_t)(b * QQ + q) * 2 + 0] * 64.0f;
    float st1 = scale[(size_t)(b * QQ + q) * 2 + 1] * 64.0f;

    float acc = 0.f;
    for (int j = 0; j < 256; j++) {
        float h = fast_gelu(fmaf(relx, sw0[j], fmaf(rely, sw0[256 + j], sb0[j])));
        acc = fmaf(h, sw1[j], acc);
    }
    g_score[m] = acc + sb1[0];
    *(float4*)(g_X + m * 4) = make_float4(relx, rely, st0, st1);
    g_gidx[m] = iy * 64 + ix;
}

// LUT: n -> (voff = k9*64+ch, kcol)
__global__ void lut_kernel() {
    int n = blockIdx.x * 256 + threadIdx.x;
    if (n < 1728) {
        int cf = n / 3, kcol = n - 3 * cf;
        int ch = cf / 9, k9 = cf - 9 * ch;
        g_lut[n] = ((k9 << 6) + ch) | (kcol << 16);
    }
}

// K3: H1 = gelu(X @ iw0 + ib0)
__global__ void h1_kernel(const float* __restrict__ iw0, const float* __restrict__ ib0) {
    size_t gid = (size_t)blockIdx.x * 256 + threadIdx.x;
    int m = (int)(gid >> 8), j = (int)(gid & 255);
    float4 x = *(const float4*)(g_X + (size_t)m * 4);
    float a = ib0[j];
    a = fmaf(x.x, iw0[j], a);
    a = fmaf(x.y, iw0[256 + j], a);
    a = fmaf(x.z, iw0[512 + j], a);
    a = fmaf(x.w, iw0[768 + j], a);
    g_H1[gid] = fast_gelu(a);
}

// ---- shared mma helpers: stage 64x32 A-tile (k-permuted tf32) ----
// kperm(k) = (k&7)*4 + (k>>3); smem row stride 48 floats (16B aligned, conflict-free)
__device__ __forceinline__ void stage_a(float* a_s, const float* __restrict__ src,
                                        int m0, int k0, int tid) {
#pragma unroll
    for (int r = 0; r < 2; r++) {
        int idx = (r << 8) + tid;
        int m = idx >> 3, kf = (idx & 7) << 2;
        float4 v = *(const float4*)(src + (size_t)(m0 + m) * 256 + k0 + kf);
        int base = m * 48;
        a_s[base + ((((kf + 0) & 7) << 2) | ((kf + 0) >> 3))] = f2tf32(v.x);
        a_s[base + ((((kf + 1) & 7) << 2) | ((kf + 1) >> 3))] = f2tf32(v.y);
        a_s[base + ((((kf + 2) & 7) << 2) | ((kf + 2) >> 3))] = f2tf32(v.z);
        a_s[base + ((((kf + 3) & 7) << 2) | ((kf + 3) >> 3))] = f2tf32(v.w);
    }
}

// K4: H2 = gelu(H1 @ iw1 + ib1)  via tf32 mma
__global__ void __launch_bounds__(256) h2_mma(const float* __restrict__ iw1,
                                              const float* __restrict__ ib1) {
    __shared__ float a_s[64 * 48];
    __shared__ float w_s[128 * 48];
    int tid = threadIdx.x, lane = tid & 31, wid = tid >> 5;
    int wm = wid >> 2, wn = wid & 3, g = lane >> 2, tg = lane & 3;
    int m0 = blockIdx.x << 6;

    for (int nb = 0; nb < 2; nb++) {
        int nbase = nb << 7;
        float d[2][4][4];
#pragma unroll
        for (int a = 0; a < 2; a++)
#pragma unroll
            for (int c = 0; c < 4; c++)
#pragma unroll
                for (int e = 0; e < 4; e++) d[a][c][e] = 0.f;

        for (int k0 = 0; k0 < 256; k0 += 32) {
            __syncthreads();
            stage_a(a_s, g_H1, m0, k0, tid);
#pragma unroll
            for (int r = 0; r < 4; r++) {
                int idx = (r << 8) + tid;
                int kk = idx >> 5, nf4 = idx & 31;
                int n = nbase + (nf4 << 2);
                float4 v = *(const float4*)(iw1 + (size_t)(k0 + kk) * 256 + n);
                int kp = ((kk & 7) << 2) | (kk >> 3);
                w_s[(nf4 * 4 + 0) * 48 + kp] = f2tf32(v.x);
                w_s[(nf4 * 4 + 1) * 48 + kp] = f2tf32(v.y);
                w_s[(nf4 * 4 + 2) * 48 + kp] = f2tf32(v.z);
                w_s[(nf4 * 4 + 3) * 48 + kp] = f2tf32(v.w);
            }
            __syncthreads();

            float4 A0[2], A1[2], A2[2], A3[2];
#pragma unroll
            for (int mf = 0; mf < 2; mf++) {
                int rr = wm * 32 + mf * 16 + g;
                A0[mf] = *(float4*)&a_s[rr * 48 + (tg << 2)];
                A2[mf] = *(float4*)&a_s[rr * 48 + ((tg + 4) << 2)];
                A1[mf] = *(float4*)&a_s[(rr + 8) * 48 + (tg << 2)];
                A3[mf] = *(float4*)&a_s[(rr + 8) * 48 + ((tg + 4) << 2)];
            }
            float4 B0[4], B1[4];
#pragma unroll
            for (int nf = 0; nf < 4; nf++) {
                int nn = wn * 32 + nf * 8 + g;
                B0[nf] = *(float4*)&w_s[nn * 48 + (tg << 2)];
                B1[nf] = *(float4*)&w_s[nn * 48 + ((tg + 4) << 2)];
            }
#pragma unroll
            for (int j = 0; j < 4; j++)
#pragma unroll
                for (int mf = 0; mf < 2; mf++)
#pragma unroll
                    for (int nf = 0; nf < 4; nf++)
                        mma8(d[mf][nf], fcomp(A0[mf], j), fcomp(A1[mf], j),
                             fcomp(A2[mf], j), fcomp(A3[mf], j),
                             fcomp(B0[nf], j), fcomp(B1[nf], j));
        }
        // epilogue: gelu + store
#pragma unroll
        for (int nf = 0; nf < 4; nf++) {
#pragma unroll
            for (int c = 0; c < 2; c++) {
                int n = nbase + wn * 32 + nf * 8 + (tg << 1) + c;
                float bias = ib1[n];
#pragma unroll
                for (int mf = 0; mf < 2; mf++) {
                    int m = m0 + wm * 32 + mf * 16 + g;
                    g_H2[(size_t)m * 256 + n] = fast_gelu(d[mf][nf][c] + bias);
                    g_H2[(size_t)(m + 8) * 256 + n] = fast_gelu(d[mf][nf][2 + c] + bias);
                }
            }
        }
    }
}

// K5: fused big GEMM (tf32 mma) + value contraction + weight MLP
__global__ void __launch_bounds__(256) big_mma(const float* __restrict__ iw2,
                                               const float* __restrict__ ib2,
                                               const float* __restrict__ ww0,
                                               const float* __restrict__ wb0,
                                               const float* __restrict__ ww1,
                                               const float* __restrict__ wb1,
                                               float* __restrict__ out) {
    extern __shared__ float sm[];
    float* val_s  = sm;                  // 64*576 = 36864
    float* a_s    = sm + 36864;          // 3072
    float* w_s    = sm + 39936;          // 6144
    float* part   = sm + 46080;          // 4*192 = 768
    float* pred_s = sm + 46848;          // 192
    float* score_s = sm + 47040;         // 64
    int*   gidx_s  = (int*)(sm + 47104); // 64

    int tid = threadIdx.x, lane = tid & 31, wid = tid >> 5;
    int wm = wid >> 2, wn = wid & 3, g = lane >> 2, tg = lane & 3;
    int m0 = blockIdx.x << 6;
    int b = m0 >> 15;

    if (tid < 64) {
        gidx_s[tid] = g_gidx[m0 + tid];
        score_s[tid] = g_score[m0 + tid];
    }
    __syncthreads();

    // gather value: 64 rows x 9 neighbors x 64 ch
    for (int wi = tid; wi < 9216; wi += 256) {
        int seg = wi >> 4, f4 = wi & 15;
        int mi = seg / 9, kk = seg - mi * 9;
        int gg = gidx_s[mi];
        int yy = (gg >> 6) + kk / 3 - 1;
        int xx = (gg & 63) + (kk % 3) - 1;
        float4 v = make_float4(0.f, 0.f, 0.f, 0.f);
        if (yy >= 0 && yy < 64 && xx >= 0 && xx < 64)
            v = *(const float4*)&g_feat[(size_t)(((b * 64 + yy) * 64 + xx) << 6) + (f4 << 2)];
        *(float4*)&val_s[mi * 576 + (kk << 6) + (f4 << 2)] = v;
    }

    float po[2][2][3];
#pragma unroll
    for (int a = 0; a < 2; a++)
#pragma unroll
        for (int h = 0; h < 2; h++)
#pragma unroll
            for (int c = 0; c < 3; c++) po[a][h][c] = 0.f;

    for (int nb = 0; nb < 14; nb++) {
        int nbase = nb << 7;
        float d[2][4][4];
#pragma unroll
        for (int a = 0; a < 2; a++)
#pragma unroll
            for (int c = 0; c < 4; c++)
#pragma unroll
                for (int e = 0; e < 4; e++) d[a][c][e] = 0.f;

        for (int k0 = 0; k0 < 256; k0 += 32) {
            __syncthreads();
            stage_a(a_s, g_H2, m0, k0, tid);
#pragma unroll
            for (int r = 0; r < 4; r++) {
                int idx = (r << 8) + tid;
                int kk = idx >> 5, nf4 = idx & 31;
                int n = nbase + (nf4 << 2);
                float4 v = make_float4(0.f, 0.f, 0.f, 0.f);
                if (n < 1728)
                    v = *(const float4*)(iw2 + (size_t)(k0 + kk) * 1728 + n);
                int kp = ((kk & 7) << 2) | (kk >> 3);
                w_s[(nf4 * 4 + 0) * 48 + kp] = f2tf32(v.x);
                w_s[(nf4 * 4 + 1) * 48 + kp] = f2tf32(v.y);
                w_s[(nf4 * 4 + 2) * 48 + kp] = f2tf32(v.z);
                w_s[(nf4 * 4 + 3) * 48 + kp] = f2tf32(v.w);
            }
            __syncthreads();

            float4 A0[2], A1[2], A2[2], A3[2];
#pragma unroll
            for (int mf = 0; mf < 2; mf++) {
                int rr = wm * 32 + mf * 16 + g;
                A0[mf] = *(float4*)&a_s[rr * 48 + (tg << 2)];
                A2[mf] = *(float4*)&a_s[rr * 48 + ((tg + 4) << 2)];
                A1[mf] = *(float4*)&a_s[(rr + 8) * 48 + (tg << 2)];
                A3[mf] = *(float4*)&a_s[(rr + 8) * 48 + ((tg + 4) << 2)];
            }
            float4 B0[4], B1[4];
#pragma unroll
            for (int nf = 0; nf < 4; nf++) {
                int nn = wn * 32 + nf * 8 + g;
                B0[nf] = *(float4*)&w_s[nn * 48 + (tg << 2)];
                B1[nf] = *(float4*)&w_s[nn * 48 + ((tg + 4) << 2)];
            }
#pragma unroll
            for (int j = 0; j < 4; j++)
#pragma unroll
                for (int mf = 0; mf < 2; mf++)
#pragma unroll
                    for (int nf = 0; nf < 4; nf++)
                        mma8(d[mf][nf], fcomp(A0[mf], j), fcomp(A1[mf], j),
                             fcomp(A2[mf], j), fcomp(A3[mf], j),
                             fcomp(B0[nf], j), fcomp(B1[nf], j));
        }

        // fused contraction epilogue
#pragma unroll
        for (int nf = 0; nf < 4; nf++) {
            int n0 = nbase + wn * 32 + nf * 8 + (tg << 1);
#pragma unroll
            for (int c = 0; c < 2; c++) {
                int n = n0 + c;
                if (n < 1728) {
                    int lut = g_lut[n];
                    int voff = lut & 0xFFFF, kcol = lut >> 16;
                    float bias = ib2[n];
#pragma unroll
                    for (int mf = 0; mf < 2; mf++) {
                        int lr = wm * 32 + mf * 16 + g;
                        float p0 = (d[mf][nf][c] + bias) * val_s[lr * 576 + voff];
                        float p1 = (d[mf][nf][2 + c] + bias) * val_s[(lr + 8) * 576 + voff];
                        if (kcol == 0)      { po[mf][0][0] += p0; po[mf][1][0] += p1; }
                        else if (kcol == 1) { po[mf][0][1] += p0; po[mf][1][1] += p1; }
                        else                { po[mf][0][2] += p0; po[mf][1][2] += p1; }
                    }
                }
            }
        }
    }

    // deterministic reduce: shfl over tg, per-wn smem partials, tree sum
#pragma unroll
    for (int mf = 0; mf < 2; mf++)
#pragma unroll
        for (int h = 0; h < 2; h++)
#pragma unroll
            for (int kc = 0; kc < 3; kc++) {
                float v = po[mf][h][kc];
                v += __shfl_xor_sync(0xffffffffu, v, 1);
                v += __shfl_xor_sync(0xffffffffu, v, 2);
                if (tg == 0)
                    part[wn * 192 + (wm * 32 + mf * 16 + h * 8 + g) * 3 + kc] = v;
            }
    __syncthreads();
    if (tid < 192) {
        int row = tid / 3;
        pred_s[tid] = score_s[row] + ((part[tid] + part[192 + tid]) +
                                      (part[384 + tid] + part[576 + tid]));
    }
    __syncthreads();

    // fused weight MLP: 16 queries x 3 outputs
    if (tid < 48) {
        int qi = tid / 3, k = tid - qi * 3;
        int base = qi * 12 + k;
        float x0 = pred_s[base], x1 = pred_s[base + 3];
        float x2 = pred_s[base + 6], x3 = pred_s[base + 9];
        float acc = wb1[0];
        for (int j = 0; j < 256; j++) {
            float h = fast_gelu(fmaf(x0, ww0[j],
                        fmaf(x1, ww0[256 + j],
                        fmaf(x2, ww0[512 + j],
                        fmaf(x3, ww0[768 + j], wb0[j])))));
            acc = fmaf(h, ww1[j], acc);
        }
        out[((m0 >> 2) + qi) * 3 + k] = acc;
    }
}

extern "C" void kernel_launch(void* const* d_in, const int* in_sizes, int n_in,
                              void* d_out, int out_size) {
    const float* inp   = (const float*)d_in[0];
    const float* coord = (const float*)d_in[1];
    const float* scale = (const float*)d_in[2];
    const float* enc_w = (const float*)d_in[3];
    const float* enc_b = (const float*)d_in[4];
    const float* iw0 = (const float*)d_in[5];
    const float* ib0 = (const float*)d_in[6];
    const float* iw1 = (const float*)d_in[7];
    const float* ib1 = (const float*)d_in[8];
    const float* iw2 = (const float*)d_in[9];
    const float* ib2 = (const float*)d_in[10];
    const float* sw0 = (const float*)d_in[11];
    const float* sb0 = (const float*)d_in[12];
    const float* sw1 = (const float*)d_in[13];
    const float* sb1 = (const float*)d_in[14];
    const float* ww0 = (const float*)d_in[15];
    const float* wb0 = (const float*)d_in[16];
    const float* ww1 = (const float*)d_in[17];
    const float* wb1 = (const float*)d_in[18];
    float* out = (float*)d_out;

    static int smem_set = 0;
    if (!smem_set) {
        cudaFuncSetAttribute(big_mma, cudaFuncAttributeMaxDynamicSharedMemorySize, 188672);
        smem_set = 1;
    }

    conv_kernel<<<8192, 64>>>(inp, enc_w, enc_b);
    prep_kernel<<<256, 256>>>(coord, scale, sw0, sb0, sw1, sb1);
    lut_kernel<<<7, 256>>>();
    h1_kernel<<<65536, 256>>>(iw0, ib0);
    h2_mma<<<1024, 256>>>(iw1, ib1);
    big_mma<<<1024, 256, 188672>>>(iw2, ib2, ww0, wb0, ww1, wb1, out);
}

// round 14
// speedup vs baseline: 1.0016x; 1.0016x over previous
#include <cuda_runtime.h>

#define BB 2
#define QQ 8192
#define MM 65536

__device__ float g_feat[BB * 64 * 64 * 64];     // channel-last [b][y][x][c]
__device__ float g_X[MM * 4];
__device__ int   g_gidx[MM];
__device__ float g_score[MM];
__device__ float g_H1[(size_t)MM * 256];
__device__ float g_H2[(size_t)MM * 256];
__device__ int   g_lut[1728];

__device__ __forceinline__ float fast_gelu(float x) {
    float u = 1.5957691216057308f * fmaf(0.044715f * x * x, x, x);
    return x * __fdividef(1.0f, 1.0f + __expf(-u));
}

__device__ __forceinline__ float f2tf32(float x) {
    unsigned u;
    asm("cvt.rna.tf32.f32 %0, %1;" : "=r"(u) : "f"(x));
    return __uint_as_float(u);
}

__device__ __forceinline__ void mma8(float* dd, unsigned a0, unsigned a1, unsigned a2,
                                     unsigned a3, unsigned b0, unsigned b1) {
    asm volatile(
        "mma.sync.aligned.m16n8k8.row.col.f32.tf32.tf32.f32 "
        "{%0,%1,%2,%3}, {%4,%5,%6,%7}, {%8,%9}, {%0,%1,%2,%3};\n"
        : "+f"(dd[0]), "+f"(dd[1]), "+f"(dd[2]), "+f"(dd[3])
        : "r"(a0), "r"(a1), "r"(a2), "r"(a3), "r"(b0), "r"(b1));
}

__device__ __forceinline__ unsigned fcomp(const float4& v, int j) {
    return __float_as_uint(((const float*)&v)[j]);
}

// K1: conv3x3 SAME + bias, channel-last feat
__global__ void conv_kernel(const float* __restrict__ inp,
                            const float* __restrict__ w,
                            const float* __restrict__ bias) {
    __shared__ float s_in[27];
    int pix = blockIdx.x;
    int b = pix >> 12, y = (pix >> 6) & 63, x = pix & 63;
    int c = threadIdx.x;
    if (c < 27) {
        int i = c / 9, kk = c - i * 9;
        int yy = y + kk / 3 - 1, xx = x + (kk % 3) - 1;
        float v = 0.f;
        if (yy >= 0 && yy < 64 && xx >= 0 && xx < 64)
            v = inp[((b * 3 + i) * 64 + yy) * 64 + xx];
        s_in[c] = v;
    }
    __syncthreads();
    float acc = bias[c];
#pragma unroll
    for (int t = 0; t < 27; t++) acc = fmaf(s_in[t], w[c * 27 + t], acc);
    g_feat[(pix << 6) + c] = acc;
}

// K2: prep + score MLP
__global__ void prep_kernel(const float* __restrict__ coord,
                            const float* __restrict__ scale,
                            const float* __restrict__ sw0,
                            const float* __restrict__ sb0,
                            const float* __restrict__ sw1,
                            const float* __restrict__ sb1) {
    int m = blockIdx.x * blockDim.x + threadIdx.x;
    if (m >= MM) return;
    int b = m >> 15, q = (m >> 2) & (QQ - 1), s = m & 3;
    float vx = (s < 2) ? -1.f : 1.f;
    float vy = (s & 1) ? 1.f : -1.f;

    float c0 = coord[(b * QQ + q) * 2 + 0];
    float c1 = coord[(b * QQ + q) * 2 + 1];
    float tx = 63.0f / (1.0f - scale[(size_t)b * QQ * 2 + 0]);
    float ty = 63.0f / (1.0f - scale[(size_t)b * QQ * 2 + 1]);
    float sh0 = vx * (1.0f / tx) + 1e-6f;
    float sh1 = vy * (1.0f / ty) + 1e-6f;

    float cc0 = fminf(fmaxf(c0 + sh0, -1.0f + 1e-6f), 1.0f - 1e-6f);
    float cc1 = fminf(fmaxf(c1 + sh1, -1.0f + 1e-6f), 1.0f - 1e-6f);
    int iy = (int)fminf(fmaxf(rintf((cc0 + 1.0f) * 32.0f - 0.5f), 0.f), 63.f);
    int ix = (int)fminf(fmaxf(rintf((cc1 + 1.0f) * 32.0f - 0.5f), 0.f), 63.f);

    float ck0 = -1.0f + (float)(2 * iy + 1) * 0.015625f;
    float ck1 = -1.0f + (float)(2 * ix + 1) * 0.015625f;
    float relx = (c0 - ck0) * 64.0f;
    float rely = (c1 - ck1) * 64.0f;
    float st0 = scale[(size_t)(b * QQ + q) * 2 + 0] * 64.0f;
    float st1 = scale[(size_t)(b * QQ + q) * 2 + 1] * 64.0f;

    float acc = 0.f;
    for (int j = 0; j < 256; j++) {
        float h = fast_gelu(fmaf(relx, sw0[j], fmaf(rely, sw0[256 + j], sb0[j])));
        acc = fmaf(h, sw1[j], acc);
    }
    g_score[m] = acc + sb1[0];
    *(float4*)(g_X + m * 4) = make_float4(relx, rely, st0, st1);
    g_gidx[m] = iy * 64 + ix;
}

// LUT: n -> (voff = k9*64+ch, kcol)
__global__ void lut_kernel() {
    int n = blockIdx.x * 256 + threadIdx.x;
    if (n < 1728) {
        int cf = n / 3, kcol = n - 3 * cf;
        int ch = cf / 9, k9 = cf - 9 * ch;
        g_lut[n] = ((k9 << 6) + ch) | (kcol << 16);
    }
}

// K3: H1 = gelu(X @ iw0 + ib0)
__global__ void h1_kernel(const float* __restrict__ iw0, const float* __restrict__ ib0) {
    size_t gid = (size_t)blockIdx.x * 256 + threadIdx.x;
    int m = (int)(gid >> 8), j = (int)(gid & 255);
    float4 x = *(const float4*)(g_X + (size_t)m * 4);
    float a = ib0[j];
    a = fmaf(x.x, iw0[j], a);
    a = fmaf(x.y, iw0[256 + j], a);
    a = fmaf(x.z, iw0[512 + j], a);
    a = fmaf(x.w, iw0[768 + j], a);
    g_H1[gid] = fast_gelu(a);
}

// ---- shared mma helpers: stage 64x32 A-tile (k-permuted tf32) ----
// kperm(k) = (k&7)*4 + (k>>3); smem row stride 48 floats (16B aligned, conflict-free)
__device__ __forceinline__ void stage_a(float* a_s, const float* __restrict__ src,
                                        int m0, int k0, int tid) {
#pragma unroll
    for (int r = 0; r < 2; r++) {
        int idx = (r << 8) + tid;
        int m = idx >> 3, kf = (idx & 7) << 2;
        float4 v = *(const float4*)(src + (size_t)(m0 + m) * 256 + k0 + kf);
        int base = m * 48;
        a_s[base + ((((kf + 0) & 7) << 2) | ((kf + 0) >> 3))] = f2tf32(v.x);
        a_s[base + ((((kf + 1) & 7) << 2) | ((kf + 1) >> 3))] = f2tf32(v.y);
        a_s[base + ((((kf + 2) & 7) << 2) | ((kf + 2) >> 3))] = f2tf32(v.z);
        a_s[base + ((((kf + 3) & 7) << 2) | ((kf + 3) >> 3))] = f2tf32(v.w);
    }
}

// K4: H2 = gelu(H1 @ iw1 + ib1)  via tf32 mma
__global__ void __launch_bounds__(256) h2_mma(const float* __restrict__ iw1,
                                              const float* __restrict__ ib1) {
    __shared__ float a_s[64 * 48];
    __shared__ float w_s[128 * 48];
    int tid = threadIdx.x, lane = tid & 31, wid = tid >> 5;
    int wm = wid >> 2, wn = wid & 3, g = lane >> 2, tg = lane & 3;
    int m0 = blockIdx.x << 6;

    for (int nb = 0; nb < 2; nb++) {
        int nbase = nb << 7;
        float d[2][4][4];
#pragma unroll
        for (int a = 0; a < 2; a++)
#pragma unroll
            for (int c = 0; c < 4; c++)
#pragma unroll
                for (int e = 0; e < 4; e++) d[a][c][e] = 0.f;

        for (int k0 = 0; k0 < 256; k0 += 32) {
            __syncthreads();
            stage_a(a_s, g_H1, m0, k0, tid);
#pragma unroll
            for (int r = 0; r < 4; r++) {
                int idx = (r << 8) + tid;
                int kk = idx >> 5, nf4 = idx & 31;
                int n = nbase + (nf4 << 2);
                float4 v = *(const float4*)(iw1 + (size_t)(k0 + kk) * 256 + n);
                int kp = ((kk & 7) << 2) | (kk >> 3);
                w_s[(nf4 * 4 + 0) * 48 + kp] = f2tf32(v.x);
                w_s[(nf4 * 4 + 1) * 48 + kp] = f2tf32(v.y);
                w_s[(nf4 * 4 + 2) * 48 + kp] = f2tf32(v.z);
                w_s[(nf4 * 4 + 3) * 48 + kp] = f2tf32(v.w);
            }
            __syncthreads();

            float4 A0[2], A1[2], A2[2], A3[2];
#pragma unroll
            for (int mf = 0; mf < 2; mf++) {
                int rr = wm * 32 + mf * 16 + g;
                A0[mf] = *(float4*)&a_s[rr * 48 + (tg << 2)];
                A2[mf] = *(float4*)&a_s[rr * 48 + ((tg + 4) << 2)];
                A1[mf] = *(float4*)&a_s[(rr + 8) * 48 + (tg << 2)];
                A3[mf] = *(float4*)&a_s[(rr + 8) * 48 + ((tg + 4) << 2)];
            }
            float4 B0[4], B1[4];
#pragma unroll
            for (int nf = 0; nf < 4; nf++) {
                int nn = wn * 32 + nf * 8 + g;
                B0[nf] = *(float4*)&w_s[nn * 48 + (tg << 2)];
                B1[nf] = *(float4*)&w_s[nn * 48 + ((tg + 4) << 2)];
            }
#pragma unroll
            for (int j = 0; j < 4; j++)
#pragma unroll
                for (int mf = 0; mf < 2; mf++)
#pragma unroll
                    for (int nf = 0; nf < 4; nf++)
                        mma8(d[mf][nf], fcomp(A0[mf], j), fcomp(A1[mf], j),
                             fcomp(A2[mf], j), fcomp(A3[mf], j),
                             fcomp(B0[nf], j), fcomp(B1[nf], j));
        }
        // epilogue: gelu + store
#pragma unroll
        for (int nf = 0; nf < 4; nf++) {
#pragma unroll
            for (int c = 0; c < 2; c++) {
                int n = nbase + wn * 32 + nf * 8 + (tg << 1) + c;
                float bias = ib1[n];
#pragma unroll
                for (int mf = 0; mf < 2; mf++) {
                    int m = m0 + wm * 32 + mf * 16 + g;
                    g_H2[(size_t)m * 256 + n] = fast_gelu(d[mf][nf][c] + bias);
                    g_H2[(size_t)(m + 8) * 256 + n] = fast_gelu(d[mf][nf][2 + c] + bias);
                }
            }
        }
    }
}

// K5: fused big GEMM (tf32 mma) + value contraction + weight MLP
__global__ void __launch_bounds__(256) big_mma(const float* __restrict__ iw2,
                                               const float* __restrict__ ib2,
                                               const float* __restrict__ ww0,
                                               const float* __restrict__ wb0,
                                               const float* __restrict__ ww1,
                                               const float* __restrict__ wb1,
                                               float* __restrict__ out) {
    extern __shared__ float sm[];
    float* val_s  = sm;                  // 64*576 = 36864
    float* a_s    = sm + 36864;          // 3072
    float* w_s    = sm + 39936;          // 6144
    float* part   = sm + 46080;          // 4*192 = 768
    float* pred_s = sm + 46848;          // 192
    float* score_s = sm + 47040;         // 64
    int*   gidx_s  = (int*)(sm + 47104); // 64

    int tid = threadIdx.x, lane = tid & 31, wid = tid >> 5;
    int wm = wid >> 2, wn = wid & 3, g = lane >> 2, tg = lane & 3;
    int m0 = blockIdx.x << 6;
    int b = m0 >> 15;

    if (tid < 64) {
        gidx_s[tid] = g_gidx[m0 + tid];
        score_s[tid] = g_score[m0 + tid];
    }
    __syncthreads();

    // gather value: 64 rows x 9 neighbors x 64 ch
    for (int wi = tid; wi < 9216; wi += 256) {
        int seg = wi >> 4, f4 = wi & 15;
        int mi = seg / 9, kk = seg - mi * 9;
        int gg = gidx_s[mi];
        int yy = (gg >> 6) + kk / 3 - 1;
        int xx = (gg & 63) + (kk % 3) - 1;
        float4 v = make_float4(0.f, 0.f, 0.f, 0.f);
        if (yy >= 0 && yy < 64 && xx >= 0 && xx < 64)
            v = *(const float4*)&g_feat[(size_t)(((b * 64 + yy) * 64 + xx) << 6) + (f4 << 2)];
        *(float4*)&val_s[mi * 576 + (kk << 6) + (f4 << 2)] = v;
    }

    float po[2][2][3];
#pragma unroll
    for (int a = 0; a < 2; a++)
#pragma unroll
        for (int h = 0; h < 2; h++)
#pragma unroll
            for (int c = 0; c < 3; c++) po[a][h][c] = 0.f;

    for (int nb = 0; nb < 14; nb++) {
        int nbase = nb << 7;
        float d[2][4][4];
#pragma unroll
        for (int a = 0; a < 2; a++)
#pragma unroll
            for (int c = 0; c < 4; c++)
#pragma unroll
                for (int e = 0; e < 4; e++) d[a][c][e] = 0.f;

        for (int k0 = 0; k0 < 256; k0 += 32) {
            __syncthreads();
            stage_a(a_s, g_H2, m0, k0, tid);
#pragma unroll
            for (int r = 0; r < 4; r++) {
                int idx = (r << 8) + tid;
                int kk = idx >> 5, nf4 = idx & 31;
                int n = nbase + (nf4 << 2);
                float4 v = make_float4(0.f, 0.f, 0.f, 0.f);
                if (n < 1728)
                    v = *(const float4*)(iw2 + (size_t)(k0 + kk) * 1728 + n);
                int kp = ((kk & 7) << 2) | (kk >> 3);
                w_s[(nf4 * 4 + 0) * 48 + kp] = f2tf32(v.x);
                w_s[(nf4 * 4 + 1) * 48 + kp] = f2tf32(v.y);
                w_s[(nf4 * 4 + 2) * 48 + kp] = f2tf32(v.z);
                w_s[(nf4 * 4 + 3) * 48 + kp] = f2tf32(v.w);
            }
            __syncthreads();

            float4 A0[2], A1[2], A2[2], A3[2];
#pragma unroll
            for (int mf = 0; mf < 2; mf++) {
                int rr = wm * 32 + mf * 16 + g;
                A0[mf] = *(float4*)&a_s[rr * 48 + (tg << 2)];
                A2[mf] = *(float4*)&a_s[rr * 48 + ((tg + 4) << 2)];
                A1[mf] = *(float4*)&a_s[(rr + 8) * 48 + (tg << 2)];
                A3[mf] = *(float4*)&a_s[(rr + 8) * 48 + ((tg + 4) << 2)];
            }
            float4 B0[4], B1[4];
#pragma unroll
            for (int nf = 0; nf < 4; nf++) {
                int nn = wn * 32 + nf * 8 + g;
                B0[nf] = *(float4*)&w_s[nn * 48 + (tg << 2)];
                B1[nf] = *(float4*)&w_s[nn * 48 + ((tg + 4) << 2)];
            }
#pragma unroll
            for (int j = 0; j < 4; j++)
#pragma unroll
                for (int mf = 0; mf < 2; mf++)
#pragma unroll
                    for (int nf = 0; nf < 4; nf++)
                        mma8(d[mf][nf], fcomp(A0[mf], j), fcomp(A1[mf], j),
                             fcomp(A2[mf], j), fcomp(A3[mf], j),
                             fcomp(B0[nf], j), fcomp(B1[nf], j));
        }

        // fused contraction epilogue
#pragma unroll
        for (int nf = 0; nf < 4; nf++) {
            int n0 = nbase + wn * 32 + nf * 8 + (tg << 1);
#pragma unroll
            for (int c = 0; c < 2; c++) {
                int n = n0 + c;
                if (n < 1728) {
                    int lut = g_lut[n];
                    int voff = lut & 0xFFFF, kcol = lut >> 16;
                    float bias = ib2[n];
#pragma unroll
                    for (int mf = 0; mf < 2; mf++) {
                        int lr = wm * 32 + mf * 16 + g;
                        float p0 = (d[mf][nf][c] + bias) * val_s[lr * 576 + voff];
                        float p1 = (d[mf][nf][2 + c] + bias) * val_s[(lr + 8) * 576 + voff];
                        if (kcol == 0)      { po[mf][0][0] += p0; po[mf][1][0] += p1; }
                        else if (kcol == 1) { po[mf][0][1] += p0; po[mf][1][1] += p1; }
                        else                { po[mf][0][2] += p0; po[mf][1][2] += p1; }
                    }
                }
            }
        }
    }

    // deterministic reduce: shfl over tg, per-wn smem partials, tree sum
#pragma unroll
    for (int mf = 0; mf < 2; mf++)
#pragma unroll
        for (int h = 0; h < 2; h++)
#pragma unroll
            for (int kc = 0; kc < 3; kc++) {
                float v = po[mf][h][kc];
                v += __shfl_xor_sync(0xffffffffu, v, 1);
                v += __shfl_xor_sync(0xffffffffu, v, 2);
                if (tg == 0)
                    part[wn * 192 + (wm * 32 + mf * 16 + h * 8 + g) * 3 + kc] = v;
            }
    __syncthreads();
    if (tid < 192) {
        int row = tid / 3;
        pred_s[tid] = score_s[row] + ((part[tid] + part[192 + tid]) +
                                      (part[384 + tid] + part[576 + tid]));
    }
    __syncthreads();

    // fused weight MLP: 16 queries x 3 outputs
    if (tid < 48) {
        int qi = tid / 3, k = tid - qi * 3;
        int base = qi * 12 + k;
        float x0 = pred_s[base], x1 = pred_s[base + 3];
        float x2 = pred_s[base + 6], x3 = pred_s[base + 9];
        float acc = wb1[0];
        for (int j = 0; j < 256; j++) {
            float h = fast_gelu(fmaf(x0, ww0[j],
                        fmaf(x1, ww0[256 + j],
                        fmaf(x2, ww0[512 + j],
                        fmaf(x3, ww0[768 + j], wb0[j])))));
            acc = fmaf(h, ww1[j], acc);
        }
        out[((m0 >> 2) + qi) * 3 + k] = acc;
    }
}

extern "C" void kernel_launch(void* const* d_in, const int* in_sizes, int n_in,
                              void* d_out, int out_size) {
    const float* inp   = (const float*)d_in[0];
    const float* coord = (const float*)d_in[1];
    const float* scale = (const float*)d_in[2];
    const float* enc_w = (const float*)d_in[3];
    const float* enc_b = (const float*)d_in[4];
    const float* iw0 = (const float*)d_in[5];
    const float* ib0 = (const float*)d_in[6];
    const float* iw1 = (const float*)d_in[7];
    const float* ib1 = (const float*)d_in[8];
    const float* iw2 = (const float*)d_in[9];
    const float* ib2 = (const float*)d_in[10];
    const float* sw0 = (const float*)d_in[11];
    const float* sb0 = (const float*)d_in[12];
    const float* sw1 = (const float*)d_in[13];
    const float* sb1 = (const float*)d_in[14];
    const float* ww0 = (const float*)d_in[15];
    const float* wb0 = (const float*)d_in[16];
    const float* ww1 = (const float*)d_in[17];
    const float* wb1 = (const float*)d_in[18];
    float* out = (float*)d_out;

    static int smem_set = 0;
    if (!smem_set) {
        cudaFuncSetAttribute(big_mma, cudaFuncAttributeMaxDynamicSharedMemorySize, 188672);
        smem_set = 1;
    }

    conv_kernel<<<8192, 64>>>(inp, enc_w, enc_b);
    prep_kernel<<<256, 256>>>(coord, scale, sw0, sb0, sw1, sb1);
    lut_kernel<<<7, 256>>>();
    h1_kernel<<<65536, 256>>>(iw0, ib0);
    h2_mma<<<1024, 256>>>(iw1, ib1);
    big_mma<<<1024, 256, 188672>>>(iw2, ib2, ww0, wb0, ww1, wb1, out);
}